// round 1
// baseline (speedup 1.0000x reference)
#include <cuda_runtime.h>

// ---------------------------------------------------------------------------
// TUPE multihead attention, fp32 SIMT baseline.
// Pipeline:
//  1) gemm_nt  x @ Wqkv^T    -> Qcat[:, 0:64]*scale, Kcat[:, 0:64], Vt  (remap epi)
//  2) gemm_nt  PE @ UqUk^T   -> Qcat[:, 64:128]*scale, Kcat[:, 64:128]  (remap epi)
//  3) gemm_nt  Qcat @ Kcat^T -> scores  (per (b,h), K=128)
//  4) softmax(scores + PE_r[h]) in place
//  5) gemm_nt  scores @ Vt^T -> vals [b,s,h*64+d]
//  6) gemm_nt  vals @ Wo^T   -> out
// ---------------------------------------------------------------------------

static constexpr int BB  = 4;
static constexpr int HH  = 8;
static constexpr int SQ  = 2048;
static constexpr int EMB = 512;
static constexpr int HD  = 64;
static constexpr float QK_SCALE = 0.0883883476483184f; // 1/sqrt(2*64)

// Scratch (device globals are the allowed scratch mechanism)
__device__ float g_Qcat[(size_t)BB * HH * SQ * 128];          //  33.5 MB
__device__ float g_Kcat[(size_t)BB * HH * SQ * 128];          //  33.5 MB
__device__ float g_Vt  [(size_t)BB * HH * HD * SQ];           //  16.8 MB (transposed: [bh, d, s])
__device__ float g_scores[(size_t)BB * HH * SQ * SQ];         // 536.9 MB
__device__ float g_vals[(size_t)BB * SQ * EMB];               //  16.8 MB

// ---------------------------------------------------------------------------
// Generic tiled NT gemm: C[m,n] = sum_k A[m*lda+k] * B[n*ldb+k]
// Shapes must be exact multiples of BM/BN/BK (they all are here).
// Epilogue functor receives (bz, m, n, value).
// ---------------------------------------------------------------------------
template <int BM, int BN, int BK, int TM, int TN, typename Epi>
__global__ void __launch_bounds__((BM / TM) * (BN / TN))
gemm_nt(const float* __restrict__ A, const float* __restrict__ B,
        int K, int lda, int ldb, long strideA, long strideB, Epi epi)
{
    constexpr int THREADS = (BM / TM) * (BN / TN);
    __shared__ __align__(16) float As[BK][BM + 4];
    __shared__ __align__(16) float Bs[BK][BN + 4];

    const int tid = threadIdx.x;
    const int bz  = blockIdx.z;

    const float* Ab = A + (long)bz * strideA + (long)blockIdx.y * BM * lda;
    const float* Bb = B + (long)bz * strideB + (long)blockIdx.x * BN * ldb;

    float acc[TM][TN];
#pragma unroll
    for (int i = 0; i < TM; i++)
#pragma unroll
        for (int j = 0; j < TN; j++) acc[i][j] = 0.0f;

    const int tr = (tid / (BN / TN)) * TM;
    const int tc = (tid % (BN / TN)) * TN;

    for (int kk = 0; kk < K; kk += BK) {
        // Load A tile (BM x BK) as float4 along K, store transposed
#pragma unroll
        for (int i = tid; i < BM * BK / 4; i += THREADS) {
            int r  = i / (BK / 4);
            int c4 = (i % (BK / 4)) * 4;
            float4 v = *reinterpret_cast<const float4*>(&Ab[(long)r * lda + kk + c4]);
            As[c4 + 0][r] = v.x;
            As[c4 + 1][r] = v.y;
            As[c4 + 2][r] = v.z;
            As[c4 + 3][r] = v.w;
        }
        // Load B tile (BN x BK)
#pragma unroll
        for (int i = tid; i < BN * BK / 4; i += THREADS) {
            int r  = i / (BK / 4);
            int c4 = (i % (BK / 4)) * 4;
            float4 v = *reinterpret_cast<const float4*>(&Bb[(long)r * ldb + kk + c4]);
            Bs[c4 + 0][r] = v.x;
            Bs[c4 + 1][r] = v.y;
            Bs[c4 + 2][r] = v.z;
            Bs[c4 + 3][r] = v.w;
        }
        __syncthreads();

#pragma unroll
        for (int k = 0; k < BK; k++) {
            float a[TM], b[TN];
#pragma unroll
            for (int i = 0; i < TM; i += 4) {
                float4 t = *reinterpret_cast<const float4*>(&As[k][tr + i]);
                a[i] = t.x; a[i + 1] = t.y; a[i + 2] = t.z; a[i + 3] = t.w;
            }
#pragma unroll
            for (int j = 0; j < TN; j += 4) {
                float4 t = *reinterpret_cast<const float4*>(&Bs[k][tc + j]);
                b[j] = t.x; b[j + 1] = t.y; b[j + 2] = t.z; b[j + 3] = t.w;
            }
#pragma unroll
            for (int i = 0; i < TM; i++)
#pragma unroll
                for (int j = 0; j < TN; j++)
                    acc[i][j] = fmaf(a[i], b[j], acc[i][j]);
        }
        __syncthreads();
    }

    const int m0 = blockIdx.y * BM + tr;
    const int n0 = blockIdx.x * BN + tc;
#pragma unroll
    for (int i = 0; i < TM; i++)
#pragma unroll
        for (int j = 0; j < TN; j++)
            epi(bz, m0 + i, n0 + j, acc[i][j]);
}

// ---------------------------------------------------------------------------
// Epilogue functors
// ---------------------------------------------------------------------------
struct EpiQKV {
    // m = b*SQ + s; n in [0, 1536): head = n/192, r = n%192
    __device__ void operator()(int, int m, int n, float v) const {
        int b = m >> 11;
        int s = m & (SQ - 1);
        int h = n / (3 * HD);
        int r = n % (3 * HD);
        long bh  = (long)(b * HH + h);
        long row = (bh * SQ + s);
        if (r < HD) {
            g_Qcat[row * 128 + r] = v * QK_SCALE;
        } else if (r < 2 * HD) {
            g_Kcat[row * 128 + (r - HD)] = v;
        } else {
            g_Vt[(bh * HD + (r - 2 * HD)) * SQ + s] = v;
        }
    }
};

struct EpiPE {
    // n in [0, 1024): head = n/128, r = n%128
    __device__ void operator()(int, int m, int n, float v) const {
        int b = m >> 11;
        int s = m & (SQ - 1);
        int h = n >> 7;
        int r = n & 127;
        long row = ((long)(b * HH + h) * SQ + s);
        if (r < HD) {
            g_Qcat[row * 128 + HD + r] = v * QK_SCALE;
        } else {
            g_Kcat[row * 128 + HD + (r - HD)] = v;
        }
    }
};

struct EpiScores {
    __device__ void operator()(int bz, int m, int n, float v) const {
        g_scores[(long)bz * SQ * SQ + (long)m * SQ + n] = v;
    }
};

struct EpiPV {
    __device__ void operator()(int bz, int m, int n, float v) const {
        int b = bz >> 3;
        int h = bz & 7;
        g_vals[((long)(b * SQ + m)) * EMB + h * HD + n] = v;
    }
};

struct EpiOut {
    float* out;
    __device__ void operator()(int, int m, int n, float v) const {
        out[(long)m * EMB + n] = v;
    }
};

// ---------------------------------------------------------------------------
// Softmax with PE_r bias, one block per attention row. Row (2048 fp32) is held
// entirely in registers (8 per thread) between the read and the write.
// ---------------------------------------------------------------------------
__global__ void __launch_bounds__(256)
softmax_bias_kernel(float* __restrict__ scores, const float* __restrict__ PE_r)
{
    const long row = blockIdx.x;                  // 0 .. B*H*S-1
    const int bh = (int)(row >> 11);
    const int h  = bh & (HH - 1);
    const int q  = (int)(row & (SQ - 1));

    float4* p4 = reinterpret_cast<float4*>(scores + row * SQ);
    const float4* b4 = reinterpret_cast<const float4*>(PE_r + ((long)h * SQ + q) * SQ);

    const int t = threadIdx.x;
    float4 va = p4[t];
    float4 vb = b4[t];
    float4 wa = p4[t + 256];
    float4 wb = b4[t + 256];
    va.x += vb.x; va.y += vb.y; va.z += vb.z; va.w += vb.w;
    wa.x += wb.x; wa.y += wb.y; wa.z += wb.z; wa.w += wb.w;

    float mx = fmaxf(fmaxf(fmaxf(va.x, va.y), fmaxf(va.z, va.w)),
                     fmaxf(fmaxf(wa.x, wa.y), fmaxf(wa.z, wa.w)));
#pragma unroll
    for (int o = 16; o > 0; o >>= 1) mx = fmaxf(mx, __shfl_xor_sync(0xffffffffu, mx, o));

    __shared__ float red_max[8];
    __shared__ float red_sum[8];
    const int w = t >> 5, l = t & 31;
    if (l == 0) red_max[w] = mx;
    __syncthreads();
    if (t < 8) {
        float m2 = red_max[t];
#pragma unroll
        for (int o = 4; o > 0; o >>= 1) m2 = fmaxf(m2, __shfl_xor_sync(0xffu, m2, o));
        red_max[t] = m2;
    }
    __syncthreads();
    mx = red_max[0];

    va.x = __expf(va.x - mx); va.y = __expf(va.y - mx);
    va.z = __expf(va.z - mx); va.w = __expf(va.w - mx);
    wa.x = __expf(wa.x - mx); wa.y = __expf(wa.y - mx);
    wa.z = __expf(wa.z - mx); wa.w = __expf(wa.w - mx);

    float s = (va.x + va.y) + (va.z + va.w) + (wa.x + wa.y) + (wa.z + wa.w);
#pragma unroll
    for (int o = 16; o > 0; o >>= 1) s += __shfl_xor_sync(0xffffffffu, s, o);
    if (l == 0) red_sum[w] = s;
    __syncthreads();
    if (t < 8) {
        float s2 = red_sum[t];
#pragma unroll
        for (int o = 4; o > 0; o >>= 1) s2 += __shfl_xor_sync(0xffu, s2, o);
        red_sum[t] = s2;
    }
    __syncthreads();
    const float inv = 1.0f / red_sum[0];

    va.x *= inv; va.y *= inv; va.z *= inv; va.w *= inv;
    wa.x *= inv; wa.y *= inv; wa.z *= inv; wa.w *= inv;
    p4[t] = va;
    p4[t + 256] = wa;
}

// ---------------------------------------------------------------------------
// Launch
// ---------------------------------------------------------------------------
extern "C" void kernel_launch(void* const* d_in, const int* in_sizes, int n_in,
                              void* d_out, int out_size)
{
    const float* x    = (const float*)d_in[0];
    const float* PE   = (const float*)d_in[1];
    const float* PE_r = (const float*)d_in[2];
    const float* Wqkv = (const float*)d_in[3];
    const float* UqUk = (const float*)d_in[4];
    const float* Wo   = (const float*)d_in[5];
    float* out = (float*)d_out;

    void* p;
    cudaGetSymbolAddress(&p, g_Qcat);   float* Qc = (float*)p;
    cudaGetSymbolAddress(&p, g_Kcat);   float* Kc = (float*)p;
    cudaGetSymbolAddress(&p, g_Vt);     float* Vt = (float*)p;
    cudaGetSymbolAddress(&p, g_scores); float* Sc = (float*)p;
    cudaGetSymbolAddress(&p, g_vals);   float* Vl = (float*)p;

    const int M = BB * SQ;              // 8192

    // 1) qkv projection: [8192,512] x [1536,512]^T
    gemm_nt<128, 128, 16, 8, 8, EpiQKV>
        <<<dim3((3 * EMB) / 128, M / 128, 1), 256>>>(
            x, Wqkv, EMB, EMB, EMB, 0, 0, EpiQKV{});

    // 2) positional projection: [8192,512] x [1024,512]^T
    gemm_nt<128, 128, 16, 8, 8, EpiPE>
        <<<dim3((2 * EMB) / 128, M / 128, 1), 256>>>(
            PE, UqUk, EMB, EMB, EMB, 0, 0, EpiPE{});

    // 3) scores: per (b,h): [2048,128] x [2048,128]^T
    gemm_nt<128, 128, 16, 8, 8, EpiScores>
        <<<dim3(SQ / 128, SQ / 128, BB * HH), 256>>>(
            Qc, Kc, 128, 128, 128, (long)SQ * 128, (long)SQ * 128, EpiScores{});

    // 4) softmax(scores + PE_r[h]) in place
    softmax_bias_kernel<<<BB * HH * SQ, 256>>>(Sc, PE_r);

    // 5) attn @ V: per (b,h): [2048,2048] x [64,2048]^T (V stored transposed)
    gemm_nt<128, 64, 16, 8, 4, EpiPV>
        <<<dim3(1, SQ / 128, BB * HH), 256>>>(
            Sc, Vt, SQ, SQ, SQ, (long)SQ * SQ, (long)HD * SQ, EpiPV{});

    // 6) out projection: [8192,512] x [512,512]^T
    gemm_nt<128, 128, 16, 8, 8, EpiOut>
        <<<dim3(EMB / 128, M / 128, 1), 256>>>(
            Vl, Wo, EMB, EMB, EMB, 0, 0, EpiOut{out});
}

// round 4
// speedup vs baseline: 2.2580x; 2.2580x over previous
#include <cuda_runtime.h>
#include <cuda_bf16.h>
#include <cstdint>

// ---------------------------------------------------------------------------
// TUPE multihead attention — bf16 split-precision (hi/lo) via mma.sync HMMA.
//  All GEMMs: D += Ahi*Bhi + Ahi*Blo + Alo*Bhi  (bf16 in, fp32 accum)
//  Operands stored packed: one u32 per element = (bf16 hi << 16) | bf16 lo.
//  (tcgen05 is unavailable: harness compiles via compute_103, no 'a' features)
// ---------------------------------------------------------------------------

static constexpr int BB  = 4;
static constexpr int HH  = 8;
static constexpr int SQ  = 2048;
static constexpr int EMB = 512;
static constexpr int HD  = 64;
static constexpr float QK_SCALE = 0.0883883476483184f; // 1/sqrt(2*64)

// ------------------------------ scratch ------------------------------------
__device__ __align__(16) unsigned g_x2  [(size_t)BB * SQ * EMB];
__device__ __align__(16) unsigned g_PE2 [(size_t)BB * SQ * EMB];
__device__ __align__(16) unsigned g_W2  [(size_t)3 * EMB * EMB];
__device__ __align__(16) unsigned g_U2  [(size_t)2 * EMB * EMB];
__device__ __align__(16) unsigned g_Wo2 [(size_t)EMB * EMB];
__device__ __align__(16) unsigned g_Qcat[(size_t)BB * HH * SQ * 128];
__device__ __align__(16) unsigned g_Kcat[(size_t)BB * HH * SQ * 128];
__device__ __align__(16) unsigned g_Vt  [(size_t)BB * HH * HD * SQ];
__device__ __align__(16) float    g_scores[(size_t)BB * HH * SQ * SQ]; // fp32 -> packed in place
__device__ __align__(16) unsigned g_vals[(size_t)BB * SQ * EMB];

// ------------------------------ helpers ------------------------------------
__device__ __forceinline__ unsigned smem_u32(const void* p) {
    unsigned a;
    asm("{ .reg .u64 t; cvta.to.shared.u64 t, %1; cvt.u32.u64 %0, t; }" : "=r"(a) : "l"(p));
    return a;
}

__device__ __forceinline__ unsigned packf(float v) {
    __nv_bfloat16 hi = __float2bfloat16(v);
    float r = v - __bfloat162float(hi);
    __nv_bfloat16 lo = __float2bfloat16(r);
    return ((unsigned)__bfloat16_as_ushort(hi) << 16) | (unsigned)__bfloat16_as_ushort(lo);
}
__device__ __forceinline__ uint4 pack4(float4 v, float sc) {
    return make_uint4(packf(v.x * sc), packf(v.y * sc), packf(v.z * sc), packf(v.w * sc));
}

__global__ void __launch_bounds__(256)
pack_kernel(const float4* __restrict__ in, uint4* __restrict__ out, int n4)
{
    int i = blockIdx.x * 256 + threadIdx.x;
    if (i < n4) out[i] = pack4(in[i], 1.0f);
}

#define LDSM4(r0, r1, r2, r3, a)                                              \
    asm volatile("ldmatrix.sync.aligned.m8n8.x4.shared.b16 {%0,%1,%2,%3}, [%4];" \
                 : "=r"(r0), "=r"(r1), "=r"(r2), "=r"(r3) : "r"(a))

#define MMA16816(c, a, b0, b1)                                                \
    asm volatile("mma.sync.aligned.m16n8k16.row.col.f32.bf16.bf16.f32 "       \
                 "{%0,%1,%2,%3}, {%4,%5,%6,%7}, {%8,%9}, {%0,%1,%2,%3};"      \
                 : "+f"((c)[0]), "+f"((c)[1]), "+f"((c)[2]), "+f"((c)[3])     \
                 : "r"((a)[0]), "r"((a)[1]), "r"((a)[2]), "r"((a)[3]),        \
                   "r"(b0), "r"(b1))

// SW64 swizzle for 64-byte rows
__device__ __forceinline__ unsigned sw64(unsigned off) {
    return off ^ ((off >> 3) & 0x30);
}

// ------------------------------ GEMM ---------------------------------------
// C[128 x 64] tile; A packed u32 [M,K], B packed u32 [N,K]; K multiple of 32.
// Stage (24KB): Ahi[128x32 bf16]@0, Alo@8192, Bhi[64x32]@16384, Blo@20480.
template <typename Epi>
__global__ void __launch_bounds__(256, 2)
gemm_hmma(const unsigned* __restrict__ A, const unsigned* __restrict__ B,
          int K, int lda, int ldb, long sA, long sB, Epi epi)
{
    extern __shared__ __align__(1024) char smem[];
    constexpr int SA_LO = 8192, SB_HI = 16384, SB_LO = 20480, STAGE = 24576;

    const int tid = threadIdx.x;
    const int l   = tid & 31;
    const int w   = tid >> 5;
    const int wm  = w & 3;        // 4 warps along M
    const int wn  = w >> 2;       // 2 warps along N
    const int m0  = wm * 32;
    const int n0  = wn * 32;
    const int bz  = blockIdx.z;
    const unsigned sbase = smem_u32(smem);

    const unsigned* Ab = A + bz * sA + (long)blockIdx.y * 128 * lda;
    const unsigned* Bb = B + bz * sB + (long)blockIdx.x * 64 * ldb;

    float acc[2][4][4];
#pragma unroll
    for (int i = 0; i < 2; i++)
#pragma unroll
        for (int j = 0; j < 4; j++)
#pragma unroll
            for (int k = 0; k < 4; k++) acc[i][j][k] = 0.0f;

    // per-lane ldmatrix source coordinates
    const int arow = (l & 7) + ((l >> 3) & 1) * 8;   // + m0 + atom*16
    const int akp  = ((l >> 4) & 1) * 16;            // byte offset within kstep
    const int brow = (l & 7) + ((l >> 4) & 1) * 8;   // + n0 + pair*16
    const int bkp  = ((l >> 3) & 1) * 16;

    uint4 ra[4], rb[2];
    const int nChunks = K >> 5;

    auto load_global = [&](int c) {
#pragma unroll
        for (int it = 0; it < 4; it++) {
            int idx = tid + it * 256;
            int r = idx >> 3, q = idx & 7;
            ra[it] = *reinterpret_cast<const uint4*>(Ab + (long)r * lda + c * 32 + q * 4);
        }
#pragma unroll
        for (int it = 0; it < 2; it++) {
            int idx = tid + it * 256;
            int r = idx >> 3, q = idx & 7;
            rb[it] = *reinterpret_cast<const uint4*>(Bb + (long)r * ldb + c * 32 + q * 4);
        }
    };
    auto store_stage = [&](char* buf) {
#pragma unroll
        for (int it = 0; it < 4; it++) {
            int idx = tid + it * 256;
            int r = idx >> 3, q = idx & 7;
            unsigned sw = sw64(r * 64 + q * 8);
            uint4 wv = ra[it];
            *reinterpret_cast<uint2*>(buf + sw) =
                make_uint2(__byte_perm(wv.x, wv.y, 0x7632), __byte_perm(wv.z, wv.w, 0x7632));
            *reinterpret_cast<uint2*>(buf + SA_LO + sw) =
                make_uint2(__byte_perm(wv.x, wv.y, 0x5410), __byte_perm(wv.z, wv.w, 0x5410));
        }
#pragma unroll
        for (int it = 0; it < 2; it++) {
            int idx = tid + it * 256;
            int r = idx >> 3, q = idx & 7;
            unsigned sw = sw64(r * 64 + q * 8);
            uint4 wv = rb[it];
            *reinterpret_cast<uint2*>(buf + SB_HI + sw) =
                make_uint2(__byte_perm(wv.x, wv.y, 0x7632), __byte_perm(wv.z, wv.w, 0x7632));
            *reinterpret_cast<uint2*>(buf + SB_LO + sw) =
                make_uint2(__byte_perm(wv.x, wv.y, 0x5410), __byte_perm(wv.z, wv.w, 0x5410));
        }
    };

    load_global(0);
    store_stage(smem);
    __syncthreads();

    for (int c = 0; c < nChunks; c++) {
        const bool more = (c + 1) < nChunks;
        if (more) load_global(c + 1);

        const unsigned stage = sbase + (c & 1) * STAGE;
#pragma unroll
        for (int ks = 0; ks < 2; ks++) {
            unsigned aH[2][4], aL[2][4], bH[2][4], bL[2][4];
#pragma unroll
            for (int i = 0; i < 2; i++) {
                unsigned off = (m0 + i * 16 + arow) * 64 + ks * 32 + akp;
                unsigned sw = sw64(off);
                LDSM4(aH[i][0], aH[i][1], aH[i][2], aH[i][3], stage + sw);
                LDSM4(aL[i][0], aL[i][1], aL[i][2], aL[i][3], stage + SA_LO + sw);
            }
#pragma unroll
            for (int p = 0; p < 2; p++) {
                unsigned off = (n0 + p * 16 + brow) * 64 + ks * 32 + bkp;
                unsigned sw = sw64(off);
                LDSM4(bH[p][0], bH[p][1], bH[p][2], bH[p][3], stage + SB_HI + sw);
                LDSM4(bL[p][0], bL[p][1], bL[p][2], bL[p][3], stage + SB_LO + sw);
            }
#pragma unroll
            for (int i = 0; i < 2; i++)
#pragma unroll
                for (int j = 0; j < 4; j++) {
                    const int p = j >> 1, h = (j & 1) * 2;
                    MMA16816(acc[i][j], aH[i], bH[p][h], bH[p][h + 1]);
                    MMA16816(acc[i][j], aH[i], bL[p][h], bL[p][h + 1]);
                    MMA16816(acc[i][j], aL[i], bH[p][h], bH[p][h + 1]);
                }
        }

        if (more) store_stage(smem + ((c + 1) & 1) * STAGE);
        __syncthreads();
    }

    // ---- epilogue: stage through smem, then coalesced functor stores ----
    float* C = reinterpret_cast<float*>(smem);   // [128][68]
#pragma unroll
    for (int i = 0; i < 2; i++)
#pragma unroll
        for (int j = 0; j < 4; j++) {
            int r0  = m0 + i * 16 + (l >> 2);
            int col = n0 + j * 8 + (l & 3) * 2;
            *reinterpret_cast<float2*>(C + r0 * 68 + col)       = make_float2(acc[i][j][0], acc[i][j][1]);
            *reinterpret_cast<float2*>(C + (r0 + 8) * 68 + col) = make_float2(acc[i][j][2], acc[i][j][3]);
        }
    __syncthreads();

    {
        int r = tid >> 1, seg = (tid & 1) << 5;
        int m  = blockIdx.y * 128 + r;
        int nb = blockIdx.x * 64 + seg;
        const float* Crow = C + r * 68 + seg;
#pragma unroll
        for (int i = 0; i < 8; i++) {
            float4 v = *reinterpret_cast<const float4*>(Crow + i * 4);
            epi(bz, m, nb + i * 4, v);
        }
    }
}

// ------------------------------ epilogues ----------------------------------
struct EpiQKV {   // m in [0,8192), n in [0,1536)
    __device__ void operator()(int, int m, int n, float4 v) const {
        int b = m >> 11, s = m & (SQ - 1);
        int h = n / 192, r = n - h * 192;
        long row = ((long)(b * HH + h) * SQ + s);
        if (r < HD) {
            *reinterpret_cast<uint4*>(&g_Qcat[row * 128 + r]) = pack4(v, QK_SCALE);
        } else if (r < 2 * HD) {
            *reinterpret_cast<uint4*>(&g_Kcat[row * 128 + (r - HD)]) = pack4(v, 1.0f);
        } else {
            int d = r - 2 * HD;
            long base = ((long)(b * HH + h) * HD + d) * SQ + s;
            g_Vt[base]          = packf(v.x);
            g_Vt[base + SQ]     = packf(v.y);
            g_Vt[base + 2 * SQ] = packf(v.z);
            g_Vt[base + 3 * SQ] = packf(v.w);
        }
    }
};
struct EpiPE {    // n in [0,1024)
    __device__ void operator()(int, int m, int n, float4 v) const {
        int b = m >> 11, s = m & (SQ - 1);
        int h = n >> 7, r = n & 127;
        long row = ((long)(b * HH + h) * SQ + s);
        if (r < HD)
            *reinterpret_cast<uint4*>(&g_Qcat[row * 128 + HD + r]) = pack4(v, QK_SCALE);
        else
            *reinterpret_cast<uint4*>(&g_Kcat[row * 128 + HD + (r - HD)]) = pack4(v, 1.0f);
    }
};
struct EpiScores {
    __device__ void operator()(int bz, int m, int n, float4 v) const {
        *reinterpret_cast<float4*>(&g_scores[(long)bz * SQ * SQ + (long)m * SQ + n]) = v;
    }
};
struct EpiPV {
    __device__ void operator()(int bz, int m, int n, float4 v) const {
        int b = bz >> 3, h = bz & 7;
        *reinterpret_cast<uint4*>(&g_vals[((long)(b * SQ + m)) * EMB + h * HD + n]) = pack4(v, 1.0f);
    }
};
struct EpiOut {
    float* out;
    __device__ void operator()(int, int m, int n, float4 v) const {
        *reinterpret_cast<float4*>(&out[(long)m * EMB + n]) = v;
    }
};

// ------------------------------ softmax ------------------------------------
// reads fp32 scores + PE_r bias, writes PACKED probabilities in place.
__global__ void __launch_bounds__(256)
softmax_bias_kernel(float* __restrict__ scores, const float* __restrict__ PE_r)
{
    const long row = blockIdx.x;
    const int bh = (int)(row >> 11);
    const int h  = bh & (HH - 1);
    const int q  = (int)(row & (SQ - 1));

    float4* p4 = reinterpret_cast<float4*>(scores + row * SQ);
    const float4* b4 = reinterpret_cast<const float4*>(PE_r + ((long)h * SQ + q) * SQ);

    const int t = threadIdx.x;
    float4 va = p4[t];
    float4 vb = b4[t];
    float4 wa = p4[t + 256];
    float4 wb = b4[t + 256];
    va.x += vb.x; va.y += vb.y; va.z += vb.z; va.w += vb.w;
    wa.x += wb.x; wa.y += wb.y; wa.z += wb.z; wa.w += wb.w;

    float mx = fmaxf(fmaxf(fmaxf(va.x, va.y), fmaxf(va.z, va.w)),
                     fmaxf(fmaxf(wa.x, wa.y), fmaxf(wa.z, wa.w)));
#pragma unroll
    for (int o = 16; o > 0; o >>= 1) mx = fmaxf(mx, __shfl_xor_sync(0xffffffffu, mx, o));

    __shared__ float red_max[8];
    __shared__ float red_sum[8];
    const int w = t >> 5, l = t & 31;
    if (l == 0) red_max[w] = mx;
    __syncthreads();
    if (t < 8) {
        float m2 = red_max[t];
#pragma unroll
        for (int o = 4; o > 0; o >>= 1) m2 = fmaxf(m2, __shfl_xor_sync(0xffu, m2, o));
        red_max[t] = m2;
    }
    __syncthreads();
    mx = red_max[0];

    va.x = __expf(va.x - mx); va.y = __expf(va.y - mx);
    va.z = __expf(va.z - mx); va.w = __expf(va.w - mx);
    wa.x = __expf(wa.x - mx); wa.y = __expf(wa.y - mx);
    wa.z = __expf(wa.z - mx); wa.w = __expf(wa.w - mx);

    float s = (va.x + va.y) + (va.z + va.w) + (wa.x + wa.y) + (wa.z + wa.w);
#pragma unroll
    for (int o = 16; o > 0; o >>= 1) s += __shfl_xor_sync(0xffffffffu, s, o);
    if (l == 0) red_sum[w] = s;
    __syncthreads();
    if (t < 8) {
        float s2 = red_sum[t];
#pragma unroll
        for (int o = 4; o > 0; o >>= 1) s2 += __shfl_xor_sync(0xffu, s2, o);
        red_sum[t] = s2;
    }
    __syncthreads();
    const float inv = 1.0f / red_sum[0];

    va.x *= inv; va.y *= inv; va.z *= inv; va.w *= inv;
    wa.x *= inv; wa.y *= inv; wa.z *= inv; wa.w *= inv;

    uint4* o4 = reinterpret_cast<uint4*>(scores + row * SQ);
    o4[t]       = pack4(va, 1.0f);
    o4[t + 256] = pack4(wa, 1.0f);
}

// ------------------------------ launch -------------------------------------
template <typename Epi>
static void launch_gemm(dim3 grid, const unsigned* A, const unsigned* B, int K,
                        int lda, int ldb, long sA, long sB, Epi epi)
{
    gemm_hmma<Epi><<<grid, 256, 49152>>>(A, B, K, lda, ldb, sA, sB, epi);
}

extern "C" void kernel_launch(void* const* d_in, const int* in_sizes, int n_in,
                              void* d_out, int out_size)
{
    const float* x    = (const float*)d_in[0];
    const float* PE   = (const float*)d_in[1];
    const float* PE_r = (const float*)d_in[2];
    const float* Wqkv = (const float*)d_in[3];
    const float* UqUk = (const float*)d_in[4];
    const float* Wo   = (const float*)d_in[5];
    float* out = (float*)d_out;

    void* p;
    cudaGetSymbolAddress(&p, g_x2);     unsigned* x2  = (unsigned*)p;
    cudaGetSymbolAddress(&p, g_PE2);    unsigned* pe2 = (unsigned*)p;
    cudaGetSymbolAddress(&p, g_W2);     unsigned* w2  = (unsigned*)p;
    cudaGetSymbolAddress(&p, g_U2);     unsigned* u2  = (unsigned*)p;
    cudaGetSymbolAddress(&p, g_Wo2);    unsigned* wo2 = (unsigned*)p;
    cudaGetSymbolAddress(&p, g_Qcat);   unsigned* Qc  = (unsigned*)p;
    cudaGetSymbolAddress(&p, g_Kcat);   unsigned* Kc  = (unsigned*)p;
    cudaGetSymbolAddress(&p, g_Vt);     unsigned* Vt  = (unsigned*)p;
    cudaGetSymbolAddress(&p, g_scores); float*    Sc  = (float*)p;
    cudaGetSymbolAddress(&p, g_vals);   unsigned* Vl  = (unsigned*)p;

    auto pk = [](const float* in, unsigned* outp, long n) {
        int n4 = (int)(n / 4);
        pack_kernel<<<(n4 + 255) / 256, 256>>>((const float4*)in, (uint4*)outp, n4);
    };
    pk(x,    x2,  (long)BB * SQ * EMB);
    pk(PE,   pe2, (long)BB * SQ * EMB);
    pk(Wqkv, w2,  (long)3 * EMB * EMB);
    pk(UqUk, u2,  (long)2 * EMB * EMB);
    pk(Wo,   wo2, (long)EMB * EMB);

    // 1) qkv projection: [8192,512] x [1536,512]^T
    launch_gemm(dim3(24, 64, 1), x2, w2, EMB, EMB, EMB, 0, 0, EpiQKV{});
    // 2) positional projection: [8192,512] x [1024,512]^T
    launch_gemm(dim3(16, 64, 1), pe2, u2, EMB, EMB, EMB, 0, 0, EpiPE{});
    // 3) scores per (b,h): [2048,128] x [2048,128]^T
    launch_gemm(dim3(32, 16, BB * HH), Qc, Kc, 128, 128, 128,
                (long)SQ * 128, (long)SQ * 128, EpiScores{});
    // 4) softmax(scores + PE_r) -> packed probs in place
    softmax_bias_kernel<<<BB * HH * SQ, 256>>>(Sc, PE_r);
    // 5) attn @ V per (b,h): [2048,2048] x [64,2048]^T
    launch_gemm(dim3(1, 16, BB * HH), (const unsigned*)Sc, Vt, SQ, SQ, SQ,
                (long)SQ * SQ, (long)HD * SQ, EpiPV{});
    // 6) out projection: [8192,512] x [512,512]^T
    launch_gemm(dim3(8, 64, 1), Vl, wo2, EMB, EMB, EMB, 0, 0, EpiOut{out});
}

// round 5
// speedup vs baseline: 3.0079x; 1.3321x over previous
#include <cuda_runtime.h>
#include <cuda_bf16.h>
#include <cstdint>

// ---------------------------------------------------------------------------
// TUPE multihead attention — bf16 split-precision (hi/lo) HMMA pipeline with
// flash-attention fused middle (scores + PE_r bias + softmax + PV).
//  GEMM rule everywhere: D += Ahi*Bhi + Ahi*Blo + Alo*Bhi  (fp32 accum)
//  Operands packed: u32 = (bf16 hi << 16) | bf16 lo.
// ---------------------------------------------------------------------------

static constexpr int BB  = 4;
static constexpr int HH  = 8;
static constexpr int SQ  = 2048;
static constexpr int EMB = 512;
static constexpr int HD  = 64;
static constexpr float QK_SCALE = 0.0883883476483184f; // 1/sqrt(2*64)

// ------------------------------ scratch ------------------------------------
__device__ __align__(16) unsigned g_x2  [(size_t)BB * SQ * EMB];
__device__ __align__(16) unsigned g_PE2 [(size_t)BB * SQ * EMB];
__device__ __align__(16) unsigned g_W2  [(size_t)3 * EMB * EMB];
__device__ __align__(16) unsigned g_U2  [(size_t)2 * EMB * EMB];
__device__ __align__(16) unsigned g_Wo2 [(size_t)EMB * EMB];
__device__ __align__(16) unsigned g_Qcat[(size_t)BB * HH * SQ * 128];
__device__ __align__(16) unsigned g_Kcat[(size_t)BB * HH * SQ * 128];
__device__ __align__(16) unsigned g_Vt  [(size_t)BB * HH * HD * SQ];
__device__ __align__(16) unsigned g_vals[(size_t)BB * SQ * EMB];

// ------------------------------ helpers ------------------------------------
__device__ __forceinline__ unsigned smem_u32(const void* p) {
    unsigned a;
    asm("{ .reg .u64 t; cvta.to.shared.u64 t, %1; cvt.u32.u64 %0, t; }" : "=r"(a) : "l"(p));
    return a;
}
__device__ __forceinline__ unsigned packf(float v) {
    __nv_bfloat16 hi = __float2bfloat16(v);
    float r = v - __bfloat162float(hi);
    __nv_bfloat16 lo = __float2bfloat16(r);
    return ((unsigned)__bfloat16_as_ushort(hi) << 16) | (unsigned)__bfloat16_as_ushort(lo);
}
__device__ __forceinline__ uint4 pack4(float4 v, float sc) {
    return make_uint4(packf(v.x * sc), packf(v.y * sc), packf(v.z * sc), packf(v.w * sc));
}
// split (a,b) into bf16x2 hi frag + bf16x2 lo frag (a in low half)
__device__ __forceinline__ void split2(float a, float b, unsigned& h, unsigned& lo) {
    __nv_bfloat16 ah = __float2bfloat16(a), bh = __float2bfloat16(b);
    float ar = a - __bfloat162float(ah), br = b - __bfloat162float(bh);
    __nv_bfloat16 al = __float2bfloat16(ar), bl = __float2bfloat16(br);
    h  = ((unsigned)__bfloat16_as_ushort(bh) << 16) | (unsigned)__bfloat16_as_ushort(ah);
    lo = ((unsigned)__bfloat16_as_ushort(bl) << 16) | (unsigned)__bfloat16_as_ushort(al);
}

__global__ void __launch_bounds__(256)
pack_kernel(const float4* __restrict__ in, uint4* __restrict__ out, int n4)
{
    int i = blockIdx.x * 256 + threadIdx.x;
    if (i < n4) out[i] = pack4(in[i], 1.0f);
}

#define LDSM4(r0, r1, r2, r3, a)                                              \
    asm volatile("ldmatrix.sync.aligned.m8n8.x4.shared.b16 {%0,%1,%2,%3}, [%4];" \
                 : "=r"(r0), "=r"(r1), "=r"(r2), "=r"(r3) : "r"(a))

#define MMA16816(c, a, b0, b1)                                                \
    asm volatile("mma.sync.aligned.m16n8k16.row.col.f32.bf16.bf16.f32 "       \
                 "{%0,%1,%2,%3}, {%4,%5,%6,%7}, {%8,%9}, {%0,%1,%2,%3};"      \
                 : "+f"((c)[0]), "+f"((c)[1]), "+f"((c)[2]), "+f"((c)[3])     \
                 : "r"((a)[0]), "r"((a)[1]), "r"((a)[2]), "r"((a)[3]),        \
                   "r"(b0), "r"(b1))

#define CP_ASYNC16(dst, src) \
    asm volatile("cp.async.cg.shared.global [%0], [%1], 16;" :: "r"(dst), "l"(src))
#define CP_COMMIT() asm volatile("cp.async.commit_group;" ::: "memory")
#define CP_WAIT1()  asm volatile("cp.async.wait_group 1;" ::: "memory")

__device__ __forceinline__ unsigned sw64(unsigned off) {
    return off ^ ((off >> 3) & 0x30);
}

// ------------------------------ GEMM (projections / out) -------------------
// C[128 x 64] tile; A packed u32 [M,K], B packed u32 [N,K]; K multiple of 32.
template <typename Epi>
__global__ void __launch_bounds__(256, 2)
gemm_hmma(const unsigned* __restrict__ A, const unsigned* __restrict__ B,
          int K, int lda, int ldb, long sA, long sB, Epi epi)
{
    extern __shared__ __align__(1024) char smem[];
    constexpr int SA_LO = 8192, SB_HI = 16384, SB_LO = 20480, STAGE = 24576;

    const int tid = threadIdx.x;
    const int l   = tid & 31;
    const int w   = tid >> 5;
    const int wm  = w & 3;
    const int wn  = w >> 2;
    const int m0  = wm * 32;
    const int n0  = wn * 32;
    const int bz  = blockIdx.z;
    const unsigned sbase = smem_u32(smem);

    const unsigned* Ab = A + bz * sA + (long)blockIdx.y * 128 * lda;
    const unsigned* Bb = B + bz * sB + (long)blockIdx.x * 64 * ldb;

    float acc[2][4][4];
#pragma unroll
    for (int i = 0; i < 2; i++)
#pragma unroll
        for (int j = 0; j < 4; j++)
#pragma unroll
            for (int k = 0; k < 4; k++) acc[i][j][k] = 0.0f;

    const int arow = (l & 7) + ((l >> 3) & 1) * 8;
    const int akp  = ((l >> 4) & 1) * 16;
    const int brow = (l & 7) + ((l >> 4) & 1) * 8;
    const int bkp  = ((l >> 3) & 1) * 16;

    uint4 ra[4], rb[2];
    const int nChunks = K >> 5;

    auto load_global = [&](int c) {
#pragma unroll
        for (int it = 0; it < 4; it++) {
            int idx = tid + it * 256;
            int r = idx >> 3, q = idx & 7;
            ra[it] = *reinterpret_cast<const uint4*>(Ab + (long)r * lda + c * 32 + q * 4);
        }
#pragma unroll
        for (int it = 0; it < 2; it++) {
            int idx = tid + it * 256;
            int r = idx >> 3, q = idx & 7;
            rb[it] = *reinterpret_cast<const uint4*>(Bb + (long)r * ldb + c * 32 + q * 4);
        }
    };
    auto store_stage = [&](char* buf) {
#pragma unroll
        for (int it = 0; it < 4; it++) {
            int idx = tid + it * 256;
            int r = idx >> 3, q = idx & 7;
            unsigned sw = sw64(r * 64 + q * 8);
            uint4 wv = ra[it];
            *reinterpret_cast<uint2*>(buf + sw) =
                make_uint2(__byte_perm(wv.x, wv.y, 0x7632), __byte_perm(wv.z, wv.w, 0x7632));
            *reinterpret_cast<uint2*>(buf + SA_LO + sw) =
                make_uint2(__byte_perm(wv.x, wv.y, 0x5410), __byte_perm(wv.z, wv.w, 0x5410));
        }
#pragma unroll
        for (int it = 0; it < 2; it++) {
            int idx = tid + it * 256;
            int r = idx >> 3, q = idx & 7;
            unsigned sw = sw64(r * 64 + q * 8);
            uint4 wv = rb[it];
            *reinterpret_cast<uint2*>(buf + SB_HI + sw) =
                make_uint2(__byte_perm(wv.x, wv.y, 0x7632), __byte_perm(wv.z, wv.w, 0x7632));
            *reinterpret_cast<uint2*>(buf + SB_LO + sw) =
                make_uint2(__byte_perm(wv.x, wv.y, 0x5410), __byte_perm(wv.z, wv.w, 0x5410));
        }
    };

    load_global(0);
    store_stage(smem);
    __syncthreads();

    for (int c = 0; c < nChunks; c++) {
        const bool more = (c + 1) < nChunks;
        if (more) load_global(c + 1);

        const unsigned stage = sbase + (c & 1) * STAGE;
#pragma unroll
        for (int ks = 0; ks < 2; ks++) {
            unsigned aH[2][4], aL[2][4], bH[2][4], bL[2][4];
#pragma unroll
            for (int i = 0; i < 2; i++) {
                unsigned off = (m0 + i * 16 + arow) * 64 + ks * 32 + akp;
                unsigned sw = sw64(off);
                LDSM4(aH[i][0], aH[i][1], aH[i][2], aH[i][3], stage + sw);
                LDSM4(aL[i][0], aL[i][1], aL[i][2], aL[i][3], stage + SA_LO + sw);
            }
#pragma unroll
            for (int p = 0; p < 2; p++) {
                unsigned off = (n0 + p * 16 + brow) * 64 + ks * 32 + bkp;
                unsigned sw = sw64(off);
                LDSM4(bH[p][0], bH[p][1], bH[p][2], bH[p][3], stage + SB_HI + sw);
                LDSM4(bL[p][0], bL[p][1], bL[p][2], bL[p][3], stage + SB_LO + sw);
            }
#pragma unroll
            for (int i = 0; i < 2; i++)
#pragma unroll
                for (int j = 0; j < 4; j++) {
                    const int p = j >> 1, h = (j & 1) * 2;
                    MMA16816(acc[i][j], aH[i], bH[p][h], bH[p][h + 1]);
                    MMA16816(acc[i][j], aH[i], bL[p][h], bL[p][h + 1]);
                    MMA16816(acc[i][j], aL[i], bH[p][h], bH[p][h + 1]);
                }
        }

        if (more) store_stage(smem + ((c + 1) & 1) * STAGE);
        __syncthreads();
    }

    float* C = reinterpret_cast<float*>(smem);   // [128][68]
#pragma unroll
    for (int i = 0; i < 2; i++)
#pragma unroll
        for (int j = 0; j < 4; j++) {
            int r0  = m0 + i * 16 + (l >> 2);
            int col = n0 + j * 8 + (l & 3) * 2;
            *reinterpret_cast<float2*>(C + r0 * 68 + col)       = make_float2(acc[i][j][0], acc[i][j][1]);
            *reinterpret_cast<float2*>(C + (r0 + 8) * 68 + col) = make_float2(acc[i][j][2], acc[i][j][3]);
        }
    __syncthreads();

    {
        int r = tid >> 1, seg = (tid & 1) << 5;
        int m  = blockIdx.y * 128 + r;
        int nb = blockIdx.x * 64 + seg;
        const float* Crow = C + r * 68 + seg;
#pragma unroll
        for (int i = 0; i < 8; i++) {
            float4 v = *reinterpret_cast<const float4*>(Crow + i * 4);
            epi(bz, m, nb + i * 4, v);
        }
    }
}

struct EpiQKV {   // m in [0,8192), n in [0,1536)
    __device__ void operator()(int, int m, int n, float4 v) const {
        int b = m >> 11, s = m & (SQ - 1);
        int h = n / 192, r = n - h * 192;
        long row = ((long)(b * HH + h) * SQ + s);
        if (r < HD) {
            *reinterpret_cast<uint4*>(&g_Qcat[row * 128 + r]) = pack4(v, QK_SCALE);
        } else if (r < 2 * HD) {
            *reinterpret_cast<uint4*>(&g_Kcat[row * 128 + (r - HD)]) = pack4(v, 1.0f);
        } else {
            int d = r - 2 * HD;
            long base = ((long)(b * HH + h) * HD + d) * SQ + s;
            g_Vt[base]          = packf(v.x);
            g_Vt[base + SQ]     = packf(v.y);
            g_Vt[base + 2 * SQ] = packf(v.z);
            g_Vt[base + 3 * SQ] = packf(v.w);
        }
    }
};
struct EpiPE {    // n in [0,1024)
    __device__ void operator()(int, int m, int n, float4 v) const {
        int b = m >> 11, s = m & (SQ - 1);
        int h = n >> 7, r = n & 127;
        long row = ((long)(b * HH + h) * SQ + s);
        if (r < HD)
            *reinterpret_cast<uint4*>(&g_Qcat[row * 128 + HD + r]) = pack4(v, QK_SCALE);
        else
            *reinterpret_cast<uint4*>(&g_Kcat[row * 128 + HD + (r - HD)]) = pack4(v, 1.0f);
    }
};
struct EpiOut {
    float* out;
    __device__ void operator()(int, int m, int n, float4 v) const {
        *reinterpret_cast<float4*>(&out[(long)m * EMB + n]) = v;
    }
};

// ------------------------------ flash attention ----------------------------
// One CTA = 128 q-rows of one (b,h). 8 warps x 16 q-rows each.
// KV chunk = 64 keys. smem: K slabs (4x[64][64B] hi + lo), V slabs (2x hi+lo),
// double-buffered PE_r bias tiles via cp.async.
__global__ void __launch_bounds__(256)
flash_attn(const unsigned* __restrict__ Qc, const unsigned* __restrict__ Kc,
           const unsigned* __restrict__ Vt, const float* __restrict__ PE_r,
           unsigned* __restrict__ vals)
{
    extern __shared__ __align__(1024) char smem[];
    constexpr int SK_LO = 16384, SV_HI = 32768, SV_LO = 40960;
    constexpr int SBIAS = 49152, BIAS_STRIDE = 272, BIAS_BUF = 34816;
    constexpr int NCHUNK = SQ / 64;   // 32

    const int tid = threadIdx.x;
    const int l = tid & 31;
    const int w = tid >> 5;
    const int g = l >> 2;
    const int t = l & 3;
    const int bh = blockIdx.y;
    const int q0 = blockIdx.x * 128;
    const int qw = q0 + w * 16;
    const unsigned sbase = smem_u32(smem);

    const unsigned* Qb = Qc + ((long)bh * SQ + qw) * 128;
    const unsigned* Kb = Kc + (long)bh * SQ * 128;
    const unsigned* Vb = Vt + (long)bh * HD * SQ;
    const float* Pb = PE_r + ((long)(bh & 7) * SQ + q0) * SQ;

    // ---- Q A-frags in registers (8 k16 steps, hi/lo) ----
    unsigned qH[8][4], qL[8][4];
#pragma unroll
    for (int kc = 0; kc < 8; kc++) {
        uint2 e00 = *reinterpret_cast<const uint2*>(Qb + (long)g * 128 + kc * 16 + 2 * t);
        uint2 e10 = *reinterpret_cast<const uint2*>(Qb + (long)(g + 8) * 128 + kc * 16 + 2 * t);
        uint2 e01 = *reinterpret_cast<const uint2*>(Qb + (long)g * 128 + kc * 16 + 8 + 2 * t);
        uint2 e11 = *reinterpret_cast<const uint2*>(Qb + (long)(g + 8) * 128 + kc * 16 + 8 + 2 * t);
        qH[kc][0] = __byte_perm(e00.x, e00.y, 0x7632); qL[kc][0] = __byte_perm(e00.x, e00.y, 0x5410);
        qH[kc][1] = __byte_perm(e10.x, e10.y, 0x7632); qL[kc][1] = __byte_perm(e10.x, e10.y, 0x5410);
        qH[kc][2] = __byte_perm(e01.x, e01.y, 0x7632); qL[kc][2] = __byte_perm(e01.x, e01.y, 0x5410);
        qH[kc][3] = __byte_perm(e11.x, e11.y, 0x7632); qL[kc][3] = __byte_perm(e11.x, e11.y, 0x5410);
    }

    float oacc[8][4];
#pragma unroll
    for (int j = 0; j < 8; j++)
#pragma unroll
        for (int k = 0; k < 4; k++) oacc[j][k] = 0.0f;
    float m0r = -1e30f, m1r = -1e30f, l0r = 0.0f, l1r = 0.0f;

    const int brow = (l & 7) + ((l >> 4) & 1) * 8;
    const int bkp  = ((l >> 3) & 1) * 16;

    // prefetch bias chunk 0
    {
        unsigned base = sbase + SBIAS;
#pragma unroll
        for (int it = 0; it < 8; it++) {
            int idx = tid + it * 256;
            int r = idx >> 4, ch = idx & 15;
            CP_ASYNC16(base + r * BIAS_STRIDE + ch * 16,
                       Pb + (long)r * SQ + ch * 4);
        }
        CP_COMMIT();
    }

    for (int ck = 0; ck < NCHUNK; ck++) {
        __syncthreads();   // previous chunk's compute done reading smem

        // ---- K tile: 64 rows x 128 u32 -> hi/lo slabs ----
#pragma unroll
        for (int it = 0; it < 8; it++) {
            int idx = tid + it * 256;
            int r = idx >> 5, q = idx & 31;
            uint4 wv = *reinterpret_cast<const uint4*>(Kb + ((long)(ck * 64 + r)) * 128 + q * 4);
            unsigned off = (q >> 3) * 4096 + sw64(r * 64 + (q & 7) * 8);
            *reinterpret_cast<uint2*>(smem + off) =
                make_uint2(__byte_perm(wv.x, wv.y, 0x7632), __byte_perm(wv.z, wv.w, 0x7632));
            *reinterpret_cast<uint2*>(smem + SK_LO + off) =
                make_uint2(__byte_perm(wv.x, wv.y, 0x5410), __byte_perm(wv.z, wv.w, 0x5410));
        }
        // ---- V tile: 64 d-rows x 64 u32 -> hi/lo slabs ----
#pragma unroll
        for (int it = 0; it < 4; it++) {
            int idx = tid + it * 256;
            int r = idx >> 4, q = idx & 15;
            uint4 wv = *reinterpret_cast<const uint4*>(Vb + (long)r * SQ + ck * 64 + q * 4);
            unsigned off = (q >> 3) * 4096 + sw64(r * 64 + (q & 7) * 8);
            *reinterpret_cast<uint2*>(smem + SV_HI + off) =
                make_uint2(__byte_perm(wv.x, wv.y, 0x7632), __byte_perm(wv.z, wv.w, 0x7632));
            *reinterpret_cast<uint2*>(smem + SV_LO + off) =
                make_uint2(__byte_perm(wv.x, wv.y, 0x5410), __byte_perm(wv.z, wv.w, 0x5410));
        }
        // ---- prefetch next bias tile ----
        if (ck + 1 < NCHUNK) {
            unsigned base = sbase + SBIAS + ((ck + 1) & 1) * BIAS_BUF;
#pragma unroll
            for (int it = 0; it < 8; it++) {
                int idx = tid + it * 256;
                int r = idx >> 4, ch = idx & 15;
                CP_ASYNC16(base + r * BIAS_STRIDE + ch * 16,
                           Pb + (long)r * SQ + (ck + 1) * 64 + ch * 4);
            }
        }
        CP_COMMIT();
        CP_WAIT1();        // bias chunk ck resident
        __syncthreads();

        // ---- S = Q K^T (3-term), 128x64 per CTA, 16x64 per warp ----
        float sacc[8][4];
#pragma unroll
        for (int j = 0; j < 8; j++)
#pragma unroll
            for (int k = 0; k < 4; k++) sacc[j][k] = 0.0f;

#pragma unroll
        for (int kc = 0; kc < 8; kc++) {
            unsigned bH[4][4], bL[4][4];
            const unsigned slab = sbase + (kc >> 1) * 4096;
            const unsigned koff = (kc & 1) * 32 + bkp;
#pragma unroll
            for (int p = 0; p < 4; p++) {
                unsigned sw = sw64((p * 16 + brow) * 64 + koff);
                LDSM4(bH[p][0], bH[p][1], bH[p][2], bH[p][3], slab + sw);
                LDSM4(bL[p][0], bL[p][1], bL[p][2], bL[p][3], slab + SK_LO + sw);
            }
#pragma unroll
            for (int j = 0; j < 8; j++) {
                const int p = j >> 2, h = (j & 3);
                // map: n8 block j -> ldsm pair p=j>>1 regs (j&1)*2.. (see gemm)
            }
#pragma unroll
            for (int j = 0; j < 8; j++) {
                const int p = j >> 1, h = (j & 1) * 2;
                MMA16816(sacc[j], qH[kc], bH[p][h], bH[p][h + 1]);
                MMA16816(sacc[j], qH[kc], bL[p][h], bL[p][h + 1]);
                MMA16816(sacc[j], qL[kc], bH[p][h], bH[p][h + 1]);
            }
        }

        // ---- bias add from smem ----
        {
            const char* bb = smem + SBIAS + (ck & 1) * BIAS_BUF;
            const int r0 = w * 16 + g, r1 = r0 + 8;
#pragma unroll
            for (int j = 0; j < 8; j++) {
                float2 b0 = *reinterpret_cast<const float2*>(bb + r0 * BIAS_STRIDE + (j * 8 + 2 * t) * 4);
                float2 b1 = *reinterpret_cast<const float2*>(bb + r1 * BIAS_STRIDE + (j * 8 + 2 * t) * 4);
                sacc[j][0] += b0.x; sacc[j][1] += b0.y;
                sacc[j][2] += b1.x; sacc[j][3] += b1.y;
            }
        }

        // ---- online softmax ----
        float mx0 = -1e30f, mx1 = -1e30f;
#pragma unroll
        for (int j = 0; j < 8; j++) {
            mx0 = fmaxf(mx0, fmaxf(sacc[j][0], sacc[j][1]));
            mx1 = fmaxf(mx1, fmaxf(sacc[j][2], sacc[j][3]));
        }
        mx0 = fmaxf(mx0, __shfl_xor_sync(0xffffffffu, mx0, 1));
        mx0 = fmaxf(mx0, __shfl_xor_sync(0xffffffffu, mx0, 2));
        mx1 = fmaxf(mx1, __shfl_xor_sync(0xffffffffu, mx1, 1));
        mx1 = fmaxf(mx1, __shfl_xor_sync(0xffffffffu, mx1, 2));

        const float mn0 = fmaxf(m0r, mx0), mn1 = fmaxf(m1r, mx1);
        const float cor0 = __expf(m0r - mn0), cor1 = __expf(m1r - mn1);
        m0r = mn0; m1r = mn1;

        float sum0 = 0.0f, sum1 = 0.0f;
#pragma unroll
        for (int j = 0; j < 8; j++) {
            sacc[j][0] = __expf(sacc[j][0] - mn0);
            sacc[j][1] = __expf(sacc[j][1] - mn0);
            sacc[j][2] = __expf(sacc[j][2] - mn1);
            sacc[j][3] = __expf(sacc[j][3] - mn1);
            sum0 += sacc[j][0] + sacc[j][1];
            sum1 += sacc[j][2] + sacc[j][3];
        }
        sum0 += __shfl_xor_sync(0xffffffffu, sum0, 1);
        sum0 += __shfl_xor_sync(0xffffffffu, sum0, 2);
        sum1 += __shfl_xor_sync(0xffffffffu, sum1, 1);
        sum1 += __shfl_xor_sync(0xffffffffu, sum1, 2);
        l0r = l0r * cor0 + sum0;
        l1r = l1r * cor1 + sum1;

#pragma unroll
        for (int j = 0; j < 8; j++) {
            oacc[j][0] *= cor0; oacc[j][1] *= cor0;
            oacc[j][2] *= cor1; oacc[j][3] *= cor1;
        }

        // ---- PV: oacc += P @ V (3-term); P frags built per k16 step ----
#pragma unroll
        for (int kk = 0; kk < 4; kk++) {
            unsigned pH[4], pL[4];
            split2(sacc[2 * kk][0],     sacc[2 * kk][1],     pH[0], pL[0]);
            split2(sacc[2 * kk][2],     sacc[2 * kk][3],     pH[1], pL[1]);
            split2(sacc[2 * kk + 1][0], sacc[2 * kk + 1][1], pH[2], pL[2]);
            split2(sacc[2 * kk + 1][2], sacc[2 * kk + 1][3], pH[3], pL[3]);

            unsigned vH[4][4], vL[4][4];
            const unsigned slab = sbase + SV_HI + (kk >> 1) * 4096;
            const unsigned koff = (kk & 1) * 32 + bkp;
#pragma unroll
            for (int p = 0; p < 4; p++) {
                unsigned sw = sw64((p * 16 + brow) * 64 + koff);
                LDSM4(vH[p][0], vH[p][1], vH[p][2], vH[p][3], slab + sw);
                LDSM4(vL[p][0], vL[p][1], vL[p][2], vL[p][3], slab + (SV_LO - SV_HI) + sw);
            }
#pragma unroll
            for (int j = 0; j < 8; j++) {
                const int p = j >> 1, h = (j & 1) * 2;
                MMA16816(oacc[j], pH, vH[p][h], vH[p][h + 1]);
                MMA16816(oacc[j], pH, vL[p][h], vL[p][h + 1]);
                MMA16816(oacc[j], pL, vH[p][h], vH[p][h + 1]);
            }
        }
    }

    // ---- epilogue: out = oacc / l, packed to g_vals ----
    const float inv0 = 1.0f / l0r, inv1 = 1.0f / l1r;
    const int b = bh >> 3, h = bh & 7;
    const long row0 = (long)(b * SQ + qw + g) * EMB + h * HD;
    const long row1 = (long)(b * SQ + qw + g + 8) * EMB + h * HD;
#pragma unroll
    for (int j = 0; j < 8; j++) {
        int col = j * 8 + 2 * t;
        *reinterpret_cast<uint2*>(&vals[row0 + col]) =
            make_uint2(packf(oacc[j][0] * inv0), packf(oacc[j][1] * inv0));
        *reinterpret_cast<uint2*>(&vals[row1 + col]) =
            make_uint2(packf(oacc[j][2] * inv1), packf(oacc[j][3] * inv1));
    }
}

// ------------------------------ launch -------------------------------------
template <typename Epi>
static void launch_gemm(dim3 grid, const unsigned* A, const unsigned* B, int K,
                        int lda, int ldb, long sA, long sB, Epi epi)
{
    gemm_hmma<Epi><<<grid, 256, 49152>>>(A, B, K, lda, ldb, sA, sB, epi);
}

extern "C" void kernel_launch(void* const* d_in, const int* in_sizes, int n_in,
                              void* d_out, int out_size)
{
    const float* x    = (const float*)d_in[0];
    const float* PE   = (const float*)d_in[1];
    const float* PE_r = (const float*)d_in[2];
    const float* Wqkv = (const float*)d_in[3];
    const float* UqUk = (const float*)d_in[4];
    const float* Wo   = (const float*)d_in[5];
    float* out = (float*)d_out;

    void* p;
    cudaGetSymbolAddress(&p, g_x2);     unsigned* x2  = (unsigned*)p;
    cudaGetSymbolAddress(&p, g_PE2);    unsigned* pe2 = (unsigned*)p;
    cudaGetSymbolAddress(&p, g_W2);     unsigned* w2  = (unsigned*)p;
    cudaGetSymbolAddress(&p, g_U2);     unsigned* u2  = (unsigned*)p;
    cudaGetSymbolAddress(&p, g_Wo2);    unsigned* wo2 = (unsigned*)p;
    cudaGetSymbolAddress(&p, g_Qcat);   unsigned* Qc  = (unsigned*)p;
    cudaGetSymbolAddress(&p, g_Kcat);   unsigned* Kc  = (unsigned*)p;
    cudaGetSymbolAddress(&p, g_Vt);     unsigned* Vt  = (unsigned*)p;
    cudaGetSymbolAddress(&p, g_vals);   unsigned* Vl  = (unsigned*)p;

    auto pk = [](const float* in, unsigned* outp, long n) {
        int n4 = (int)(n / 4);
        pack_kernel<<<(n4 + 255) / 256, 256>>>((const float4*)in, (uint4*)outp, n4);
    };
    pk(x,    x2,  (long)BB * SQ * EMB);
    pk(PE,   pe2, (long)BB * SQ * EMB);
    pk(Wqkv, w2,  (long)3 * EMB * EMB);
    pk(UqUk, u2,  (long)2 * EMB * EMB);
    pk(Wo,   wo2, (long)EMB * EMB);

    // 1) qkv projection
    launch_gemm(dim3(24, 64, 1), x2, w2, EMB, EMB, EMB, 0, 0, EpiQKV{});
    // 2) positional projection
    launch_gemm(dim3(16, 64, 1), pe2, u2, EMB, EMB, EMB, 0, 0, EpiPE{});
    // 3) fused attention: scores + bias + softmax + PV
    static bool attr_set = false;
    if (!attr_set) {
        cudaFuncSetAttribute(flash_attn, cudaFuncAttributeMaxDynamicSharedMemorySize, 118784);
        attr_set = true;
    }
    flash_attn<<<dim3(SQ / 128, BB * HH), 256, 118784>>>(Qc, Kc, Vt, PE_r, Vl);
    // 4) out projection
    launch_gemm(dim3(8, 64, 1), Vl, wo2, EMB, EMB, EMB, 0, 0, EpiOut{out});
}